// round 3
// baseline (speedup 1.0000x reference)
#include <cuda_runtime.h>
#include <math.h>

#define F_IN 34
#define HID 256
#define NHEAD 8
#define HD 32
#define NLAYER 5
#define NMAX 50000
#define EMAX 800000
#define GMAX 2000

// ---------------- scratch (static __device__, no allocation) ----------------
__device__ float g_h[NMAX * HID];
__device__ float g_big[NMAX * 1024];   // GAT xl|xr [N,512] ; transformer q|k|v|skip [N,1024]
__device__ float g_t[NMAX * HID];      // temps (input embed pre-LN, out-proj pre-LN)
__device__ float g_wg[NLAYER * HID * 512];  // packed GAT weights (tf32-rounded)
__device__ float g_bg[NLAYER * 512];
__device__ float g_wt[HID * 1024];          // packed transformer weights (tf32-rounded)
__device__ float g_bt[1024];
__device__ float g_pool_sum[GMAX * HID];
__device__ float g_pool_max[GMAX * HID];
__device__ float g_cnt[GMAX];
__device__ float g_ge[GMAX * 2 * HID];
__device__ int g_deg[NMAX];
__device__ int g_rowptr[NMAX + 1];
__device__ int g_wptr[NMAX];
__device__ int g_csrc[EMAX];

// ---------------- helpers ----------------
__device__ __forceinline__ float gelu_f(float x) {
    return 0.5f * x * (1.0f + erff(x * 0.7071067811865475f));
}

__device__ __forceinline__ void atomicMaxFloat(float* addr, float value) {
    if (value >= 0.0f)
        atomicMax((int*)addr, __float_as_int(value));
    else
        atomicMin((unsigned int*)addr, __float_as_uint(value));
}

__device__ __forceinline__ float f2tf32_rna(float x) {
    unsigned r;
    asm("cvt.rna.tf32.f32 %0, %1;" : "=r"(r) : "f"(x));
    return __uint_as_float(r);
}

__device__ __forceinline__ void mma_tf32(float c[4], const unsigned a[4], unsigned b0, unsigned b1) {
    asm volatile(
        "mma.sync.aligned.m16n8k8.row.col.f32.tf32.tf32.f32 "
        "{%0,%1,%2,%3}, {%4,%5,%6,%7}, {%8,%9}, {%0,%1,%2,%3};"
        : "+f"(c[0]), "+f"(c[1]), "+f"(c[2]), "+f"(c[3])
        : "r"(a[0]), "r"(a[1]), "r"(a[2]), "r"(a[3]), "r"(b0), "r"(b1));
}

__device__ __forceinline__ void cp_async16(void* smem, const void* gmem, int src_bytes) {
    unsigned saddr = (unsigned)__cvta_generic_to_shared(smem);
    asm volatile("cp.async.cg.shared.global [%0], [%1], 16, %2;\n" ::"r"(saddr), "l"(gmem),
                 "r"(src_bytes));
}
__device__ __forceinline__ void cp_commit() { asm volatile("cp.async.commit_group;\n"); }
template <int Nw>
__device__ __forceinline__ void cp_wait() {
    asm volatile("cp.async.wait_group %0;\n" ::"n"(Nw));
}

// ---------------- weight packing (tf32-rounded) ----------------
__global__ void pack_gat_kernel(const float* __restrict__ Wl, const float* __restrict__ bl,
                                const float* __restrict__ Wr, const float* __restrict__ br) {
    int i = blockIdx.x * blockDim.x + threadIdx.x;
    if (i >= NLAYER * HID * 512) return;
    int l = i / (HID * 512);
    int r = (i / 512) % HID;
    int n = i % 512;
    float v = (n < HID) ? Wl[(l * HID + r) * HID + n] : Wr[(l * HID + r) * HID + n - HID];
    g_wg[i] = f2tf32_rna(v);
    if (r == 0) g_bg[l * 512 + n] = (n < HID) ? bl[l * HID + n] : br[l * HID + n - HID];
}

__global__ void pack_tr_kernel(const float* __restrict__ Wq, const float* __restrict__ bq,
                               const float* __restrict__ Wk, const float* __restrict__ bk,
                               const float* __restrict__ Wv, const float* __restrict__ bv,
                               const float* __restrict__ Ws, const float* __restrict__ bs) {
    int i = blockIdx.x * blockDim.x + threadIdx.x;
    if (i >= HID * 1024) return;
    int r = i / 1024;
    int n = i % 1024;
    int sel = n >> 8, cc = n & 255;
    const float* W = (sel == 0) ? Wq : (sel == 1) ? Wk : (sel == 2) ? Wv : Ws;
    const float* B = (sel == 0) ? bq : (sel == 1) ? bk : (sel == 2) ? bv : bs;
    g_wt[i] = f2tf32_rna(W[r * HID + cc]);
    if (r == 0) g_bt[n] = B[cc];
}

// ---------------- init ----------------
__global__ void init_kernel(int N, int G) {
    int i = blockIdx.x * blockDim.x + threadIdx.x;
    if (i < G * HID) {
        g_pool_sum[i] = 0.0f;
        g_pool_max[i] = -INFINITY;
    }
    if (i < G) g_cnt[i] = 0.0f;
    if (i < N) g_deg[i] = 0;
}

// ---------------- CSR build ----------------
__global__ void deg_kernel(const int* __restrict__ dst, int E) {
    int e = blockIdx.x * blockDim.x + threadIdx.x;
    if (e < E) atomicAdd(&g_deg[dst[e]], 1);
}

__global__ void scan_kernel(int N) {
    __shared__ int sdata[1024];
    __shared__ int carry;
    if (threadIdx.x == 0) carry = 0;
    __syncthreads();
    for (int base = 0; base < N; base += 1024) {
        int i = base + threadIdx.x;
        int v = (i < N) ? g_deg[i] : 0;
        sdata[threadIdx.x] = v;
        __syncthreads();
        for (int off = 1; off < 1024; off <<= 1) {
            int t = (threadIdx.x >= off) ? sdata[threadIdx.x - off] : 0;
            __syncthreads();
            sdata[threadIdx.x] += t;
            __syncthreads();
        }
        int incl = sdata[threadIdx.x];
        int excl = incl - v;
        if (i < N) {
            g_rowptr[i] = carry + excl;
            g_wptr[i] = carry + excl;
        }
        __syncthreads();
        if (threadIdx.x == 1023) carry += sdata[1023];
        __syncthreads();
    }
    if (threadIdx.x == 0) g_rowptr[N] = carry;
}

__global__ void scatter_kernel(const int* __restrict__ src, const int* __restrict__ dst, int E) {
    int e = blockIdx.x * blockDim.x + threadIdx.x;
    if (e >= E) return;
    int d = dst[e];
    int pos = atomicAdd(&g_wptr[d], 1);
    g_csrc[pos] = src[e];
}

// ---------------- fp32 SGEMM (small / precision-critical GEMMs) ----------------
#define BM 64
#define BN 64
#define BK 16
__global__ void gemm_bias_kernel(const float* __restrict__ A, const float* __restrict__ B,
                                 const float* __restrict__ bias, float* __restrict__ C,
                                 int M, int K, int Nc) {
    __shared__ float As[BK][BM + 1];
    __shared__ float Bs[BK][BN];
    int tid = threadIdx.x;
    int tx = tid & 15, ty = tid >> 4;
    int rowBase = blockIdx.y * BM;
    int colBase = blockIdx.x * BN;
    float acc[4][4];
#pragma unroll
    for (int i = 0; i < 4; i++)
#pragma unroll
        for (int j = 0; j < 4; j++) acc[i][j] = 0.0f;

    for (int k0 = 0; k0 < K; k0 += BK) {
#pragma unroll
        for (int it = 0; it < 4; it++) {
            int e = tid + it * 256;
            int kk = e % BK, mm = e / BK;
            int r = rowBase + mm, kz = k0 + kk;
            As[kk][mm] = (r < M && kz < K) ? A[(size_t)r * K + kz] : 0.0f;
        }
#pragma unroll
        for (int it = 0; it < 4; it++) {
            int e = tid + it * 256;
            int nn = e % BN, kk = e / BN;
            int kz = k0 + kk, cc = colBase + nn;
            Bs[kk][nn] = (kz < K && cc < Nc) ? B[(size_t)kz * Nc + cc] : 0.0f;
        }
        __syncthreads();
#pragma unroll
        for (int kk = 0; kk < BK; kk++) {
            float a[4], b[4];
#pragma unroll
            for (int i = 0; i < 4; i++) a[i] = As[kk][ty * 4 + i];
#pragma unroll
            for (int j = 0; j < 4; j++) b[j] = Bs[kk][tx * 4 + j];
#pragma unroll
            for (int i = 0; i < 4; i++)
#pragma unroll
                for (int j = 0; j < 4; j++) acc[i][j] += a[i] * b[j];
        }
        __syncthreads();
    }
#pragma unroll
    for (int i = 0; i < 4; i++) {
        int r = rowBase + ty * 4 + i;
        if (r >= M) continue;
#pragma unroll
        for (int j = 0; j < 4; j++) {
            int cc = colBase + tx * 4 + j;
            if (cc < Nc) C[(size_t)r * Nc + cc] = acc[i][j] + bias[cc];
        }
    }
}

// ---------------- tf32 tensor-core GEMM, cp.async 2-stage ----------------
// C[M,Nc] = A[M,K] @ B[K,Nc] + bias.  Requires Nc % 128 == 0, K % 16 == 0.
#define TBM 128
#define TBN 128
#define TBK 16
#define A_LD 20    // padded row stride (floats): conflict-free fragment loads
#define B_LD 136
__global__ __launch_bounds__(256) void gemm_tf32_kernel(
    const float* __restrict__ A, const float* __restrict__ B,
    const float* __restrict__ bias, float* __restrict__ C,
    int M, int K, int Nc) {
    __shared__ float As[2][TBM][A_LD];
    __shared__ float Bs[2][TBK][B_LD];

    int tid = threadIdx.x;
    int lane = tid & 31;
    int warp = tid >> 5;
    int warp_m = warp & 3;   // 4 warp rows x 32
    int warp_n = warp >> 2;  // 2 warp cols x 64
    int rowBase = blockIdx.y * TBM;
    int colBase = blockIdx.x * TBN;
    int kIters = K / TBK;

    float acc[2][8][4];
#pragma unroll
    for (int mt = 0; mt < 2; mt++)
#pragma unroll
        for (int nt = 0; nt < 8; nt++)
#pragma unroll
            for (int i = 0; i < 4; i++) acc[mt][nt][i] = 0.0f;

    auto issue = [&](int st, int it) {
        int k0 = it * TBK;
#pragma unroll
        for (int i = 0; i < 2; i++) {
            int q = tid + i * 256;
            int r = q >> 2, kq = q & 3;
            int gr = rowBase + r;
            int grc = (gr < M) ? gr : (M - 1);
            cp_async16(&As[st][r][kq * 4], A + (size_t)grc * K + k0 + kq * 4,
                       (gr < M) ? 16 : 0);
        }
#pragma unroll
        for (int i = 0; i < 2; i++) {
            int q = tid + i * 256;
            int kk = q >> 5, n4 = q & 31;
            cp_async16(&Bs[st][kk][n4 * 4], B + (size_t)(k0 + kk) * Nc + colBase + n4 * 4, 16);
        }
    };

    issue(0, 0);
    cp_commit();

    for (int it = 0; it < kIters; it++) {
        if (it + 1 < kIters) {
            issue((it + 1) & 1, it + 1);
            cp_commit();
            cp_wait<1>();
        } else {
            cp_wait<0>();
        }
        __syncthreads();
        int buf = it & 1;
#pragma unroll
        for (int ks = 0; ks < 2; ks++) {
            int kk = ks * 8;
            unsigned afr[2][4];
#pragma unroll
            for (int mt = 0; mt < 2; mt++) {
                int row = warp_m * 32 + mt * 16 + (lane >> 2);
                afr[mt][0] = __float_as_uint(As[buf][row][kk + (lane & 3)]);
                afr[mt][1] = __float_as_uint(As[buf][row + 8][kk + (lane & 3)]);
                afr[mt][2] = __float_as_uint(As[buf][row][kk + 4 + (lane & 3)]);
                afr[mt][3] = __float_as_uint(As[buf][row + 8][kk + 4 + (lane & 3)]);
            }
#pragma unroll
            for (int nt = 0; nt < 8; nt++) {
                int n = warp_n * 64 + nt * 8 + (lane >> 2);
                unsigned b0 = __float_as_uint(Bs[buf][kk + (lane & 3)][n]);
                unsigned b1 = __float_as_uint(Bs[buf][kk + 4 + (lane & 3)][n]);
                mma_tf32(acc[0][nt], afr[0], b0, b1);
                mma_tf32(acc[1][nt], afr[1], b0, b1);
            }
        }
        __syncthreads();
    }

    // epilogue: bias + store
#pragma unroll
    for (int mt = 0; mt < 2; mt++) {
#pragma unroll
        for (int half = 0; half < 2; half++) {
            int r = rowBase + warp_m * 32 + mt * 16 + (lane >> 2) + half * 8;
            if (r >= M) continue;
#pragma unroll
            for (int nt = 0; nt < 8; nt++) {
                int cc = colBase + warp_n * 64 + nt * 8 + 2 * (lane & 3);
                float2 v;
                v.x = acc[mt][nt][half * 2 + 0] + bias[cc];
                v.y = acc[mt][nt][half * 2 + 1] + bias[cc + 1];
                *(float2*)(C + (size_t)r * Nc + cc) = v;
            }
        }
    }
}

// ---------------- LayerNorm (+ optional GELU) ----------------
template <int DIM, bool ACT>
__global__ void ln_kernel(const float* __restrict__ in, const float* __restrict__ g,
                          const float* __restrict__ b, float* __restrict__ out) {
    int n = blockIdx.x, c = threadIdx.x;
    float v = in[n * DIM + c];
    __shared__ float sh[DIM];
    sh[c] = v;
    __syncthreads();
    for (int off = DIM / 2; off > 0; off >>= 1) {
        if (c < off) sh[c] += sh[c + off];
        __syncthreads();
    }
    float mean = sh[0] * (1.0f / DIM);
    __syncthreads();
    float d = v - mean;
    sh[c] = d * d;
    __syncthreads();
    for (int off = DIM / 2; off > 0; off >>= 1) {
        if (c < off) sh[c] += sh[c + off];
        __syncthreads();
    }
    float var = sh[0] * (1.0f / DIM);
    float y = d * rsqrtf(var + 1e-5f) * g[c] + b[c];
    if (ACT) y = gelu_f(y);
    out[n * DIM + c] = y;
}

// ---------------- GATv2 layer: 4-edge-ILP online softmax, fused LN+GELU+residual ----------------
__global__ void gat_kernel(const float* __restrict__ ab,  // [N,512]: xl | xr
                           const float* __restrict__ att, const float* __restrict__ bias,
                           const float* __restrict__ lng, const float* __restrict__ lnb,
                           float* __restrict__ h) {
    int n = blockIdx.x;
    int c = threadIdx.x;
    float xr_c = ab[n * 512 + 256 + c];
    float att_c = att[c];
    float m = -INFINITY, den = 0.0f, acc = 0.0f;
    int beg = g_rowptr[n];
    int cnt = g_rowptr[n + 1] - beg + 1;  // + self loop (last slot)
    for (int i = 0; i < cnt; i += 4) {
        float p[4], xlc[4];
#pragma unroll
        for (int u = 0; u < 4; u++) {
            int idx = i + u;
            if (idx < cnt) {
                int s = (idx < cnt - 1) ? g_csrc[beg + idx] : n;
                xlc[u] = ab[s * 512 + c];
                float t = xlc[u] + xr_c;
                t = (t > 0.0f) ? t : 0.2f * t;
                p[u] = t * att_c;
            } else {
                xlc[u] = 0.0f;
                p[u] = -INFINITY;
            }
        }
#pragma unroll
        for (int o = 16; o > 0; o >>= 1) {
#pragma unroll
            for (int u = 0; u < 4; u++) p[u] += __shfl_xor_sync(0xffffffffu, p[u], o);
        }
#pragma unroll
        for (int u = 0; u < 4; u++) {
            float mn = fmaxf(m, p[u]);
            float sc = __expf(m - mn);
            float w = __expf(p[u] - mn);
            acc = acc * sc + w * xlc[u];
            den = den * sc + w;
            m = mn;
        }
    }
    float out = acc / (den + 1e-16f) + bias[c];
    __shared__ float sh[HID];
    sh[c] = out;
    __syncthreads();
    for (int off = HID / 2; off > 0; off >>= 1) {
        if (c < off) sh[c] += sh[c + off];
        __syncthreads();
    }
    float mean = sh[0] * (1.0f / HID);
    __syncthreads();
    float d = out - mean;
    sh[c] = d * d;
    __syncthreads();
    for (int off = HID / 2; off > 0; off >>= 1) {
        if (c < off) sh[c] += sh[c + off];
        __syncthreads();
    }
    float var = sh[0] * (1.0f / HID);
    float y = d * rsqrtf(var + 1e-5f) * lng[c] + lnb[c];
    h[n * HID + c] += gelu_f(y);
}

// ---------------- TransformerConv: 4-edge-ILP, fused LN+residual ----------------
__global__ void trans_kernel(const float* __restrict__ qkvs,  // [N,1024]: q|k|v|skip
                             const float* __restrict__ lng, const float* __restrict__ lnb,
                             float* __restrict__ h) {
    int n = blockIdx.x;
    int c = threadIdx.x;
    const float scale = 0.17677669529663687f;  // 1/sqrt(32)
    float q_c = qkvs[n * 1024 + c];
    float m = -INFINITY, den = 0.0f, acc = 0.0f;
    int beg = g_rowptr[n];
    int cnt = g_rowptr[n + 1] - beg;  // no self loops
    for (int i = 0; i < cnt; i += 4) {
        float p[4], vc[4];
#pragma unroll
        for (int u = 0; u < 4; u++) {
            int idx = i + u;
            if (idx < cnt) {
                int s = g_csrc[beg + idx];
                p[u] = q_c * qkvs[s * 1024 + 256 + c];
                vc[u] = qkvs[s * 1024 + 512 + c];
            } else {
                p[u] = -INFINITY;
                vc[u] = 0.0f;
            }
        }
#pragma unroll
        for (int o = 16; o > 0; o >>= 1) {
#pragma unroll
            for (int u = 0; u < 4; u++) p[u] += __shfl_xor_sync(0xffffffffu, p[u], o);
        }
#pragma unroll
        for (int u = 0; u < 4; u++) {
            float pv = p[u] * scale;
            float mn = fmaxf(m, pv);
            float sc = __expf(m - mn);
            float w = __expf(pv - mn);
            acc = acc * sc + w * vc[u];
            den = den * sc + w;
            m = mn;
        }
    }
    float out = acc / (den + 1e-16f) + qkvs[n * 1024 + 768 + c];
    __shared__ float sh[HID];
    sh[c] = out;
    __syncthreads();
    for (int off = HID / 2; off > 0; off >>= 1) {
        if (c < off) sh[c] += sh[c + off];
        __syncthreads();
    }
    float mean = sh[0] * (1.0f / HID);
    __syncthreads();
    float d = out - mean;
    sh[c] = d * d;
    __syncthreads();
    for (int off = HID / 2; off > 0; off >>= 1) {
        if (c < off) sh[c] += sh[c + off];
        __syncthreads();
    }
    float var = sh[0] * (1.0f / HID);
    float y = d * rsqrtf(var + 1e-5f) * lng[c] + lnb[c];
    h[n * HID + c] += y;
}

// ---------------- pooling ----------------
__global__ void pool_kernel(const float* __restrict__ h, const int* __restrict__ batch) {
    int n = blockIdx.x, c = threadIdx.x;
    int g = batch[n];
    float v = h[n * HID + c];
    atomicAdd(&g_pool_sum[g * HID + c], v);
    atomicMaxFloat(&g_pool_max[g * HID + c], v);
    if (c == 0) atomicAdd(&g_cnt[g], 1.0f);
}

__global__ void finalize_kernel(int G) {
    int i = blockIdx.x * blockDim.x + threadIdx.x;
    if (i >= G * 2 * HID) return;
    int g = i / (2 * HID), c = i % (2 * HID);
    float v;
    if (c < HID) {
        v = g_pool_sum[g * HID + c] / fmaxf(g_cnt[g], 1.0f);
    } else {
        v = g_pool_max[g * HID + (c - HID)];
        if (!isfinite(v)) v = 0.0f;
    }
    g_ge[i] = v;
}

// ---------------- launch ----------------
static void run_gemm_f32(const float* A, const float* B, const float* bias, float* C,
                         int M, int K, int Nc) {
    dim3 grid((Nc + BN - 1) / BN, (M + BM - 1) / BM);
    gemm_bias_kernel<<<grid, 256>>>(A, B, bias, C, M, K, Nc);
}

static void run_gemm_tc(const float* A, const float* B, const float* bias, float* C,
                        int M, int K, int Nc) {
    dim3 grid(Nc / TBN, (M + TBM - 1) / TBM);
    gemm_tf32_kernel<<<grid, 256>>>(A, B, bias, C, M, K, Nc);
}

extern "C" void kernel_launch(void* const* d_in, const int* in_sizes, int n_in,
                              void* d_out, int out_size) {
    const float* x = (const float*)d_in[0];
    const int* ei = (const int*)d_in[1];
    const int* batch = (const int*)d_in[2];
    const float* in_W = (const float*)d_in[3];
    const float* in_b = (const float*)d_in[4];
    const float* in_ln_g = (const float*)d_in[5];
    const float* in_ln_b = (const float*)d_in[6];
    const float* gat_Wl = (const float*)d_in[7];
    const float* gat_bl = (const float*)d_in[8];
    const float* gat_Wr = (const float*)d_in[9];
    const float* gat_br = (const float*)d_in[10];
    const float* gat_att = (const float*)d_in[11];
    const float* gat_bias = (const float*)d_in[12];
    const float* gat_ln_g = (const float*)d_in[13];
    const float* gat_ln_b = (const float*)d_in[14];
    const float* tr_Wq = (const float*)d_in[15];
    const float* tr_bq = (const float*)d_in[16];
    const float* tr_Wk = (const float*)d_in[17];
    const float* tr_bk = (const float*)d_in[18];
    const float* tr_Wv = (const float*)d_in[19];
    const float* tr_bv = (const float*)d_in[20];
    const float* tr_Wskip = (const float*)d_in[21];
    const float* tr_bskip = (const float*)d_in[22];
    const float* tr_ln_g = (const float*)d_in[23];
    const float* tr_ln_b = (const float*)d_in[24];
    const float* out_W = (const float*)d_in[25];
    const float* out_b = (const float*)d_in[26];
    const float* out_ln_g = (const float*)d_in[27];
    const float* out_ln_b = (const float*)d_in[28];

    int N = in_sizes[0] / F_IN;
    int E = in_sizes[1] / 2;
    int G = out_size / (2 * HID);
    const int* src = ei;
    const int* dst = ei + E;

    float *hP, *bigP, *tP, *geP, *wgP, *bgP, *wtP, *btP;
    cudaGetSymbolAddress((void**)&hP, g_h);
    cudaGetSymbolAddress((void**)&bigP, g_big);
    cudaGetSymbolAddress((void**)&tP, g_t);
    cudaGetSymbolAddress((void**)&geP, g_ge);
    cudaGetSymbolAddress((void**)&wgP, g_wg);
    cudaGetSymbolAddress((void**)&bgP, g_bg);
    cudaGetSymbolAddress((void**)&wtP, g_wt);
    cudaGetSymbolAddress((void**)&btP, g_bt);

    // 0: pack GAT weights
    pack_gat_kernel<<<(NLAYER * HID * 512 + 255) / 256, 256>>>(gat_Wl, gat_bl, gat_Wr, gat_br);
    // 1-2: input embed (K=34, fp32): h = gelu(LN(x @ in_W + in_b))
    run_gemm_f32(x, in_W, in_b, tP, N, F_IN, HID);
    ln_kernel<HID, true><<<N, HID>>>(tP, in_ln_g, in_ln_b, hP);
    // 3: first GAT GEMM (profiled launch slot)
    run_gemm_tc(hP, wgP, bgP, bigP, N, HID, 512);
    // 4: init pools/deg
    int initN = (G * HID > N) ? G * HID : N;
    init_kernel<<<(initN + 255) / 256, 256>>>(N, G);
    // 5-7: build CSR by destination
    deg_kernel<<<(E + 255) / 256, 256>>>(dst, E);
    scan_kernel<<<1, 1024>>>(N);
    scatter_kernel<<<(E + 255) / 256, 256>>>(src, dst, E);
    // 8: GAT layer 0 aggregate
    gat_kernel<<<N, HID>>>(bigP, gat_att, gat_bias, gat_ln_g, gat_ln_b, hP);
    // layers 1..4
    for (int l = 1; l < NLAYER; l++) {
        run_gemm_tc(hP, wgP + (size_t)l * HID * 512, bgP + (size_t)l * 512, bigP, N, HID, 512);
        gat_kernel<<<N, HID>>>(bigP, gat_att + (size_t)l * HID, gat_bias + (size_t)l * HID,
                               gat_ln_g + (size_t)l * HID, gat_ln_b + (size_t)l * HID, hP);
    }

    // TransformerConv: one packed GEMM -> q|k|v|skip
    pack_tr_kernel<<<(HID * 1024 + 255) / 256, 256>>>(tr_Wq, tr_bq, tr_Wk, tr_bk, tr_Wv, tr_bv,
                                                      tr_Wskip, tr_bskip);
    run_gemm_tc(hP, wtP, btP, bigP, N, HID, 1024);
    trans_kernel<<<N, HID>>>(bigP, tr_ln_g, tr_ln_b, hP);

    // pooling
    pool_kernel<<<N, HID>>>(hP, batch);
    finalize_kernel<<<(G * 2 * HID + 255) / 256, 256>>>(G);

    // output projection (fp32) + LN + GELU
    run_gemm_f32(geP, out_W, out_b, tP, G, 2 * HID, 2 * HID);
    ln_kernel<2 * HID, true><<<G, 2 * HID>>>(tP, out_ln_g, out_ln_b, (float*)d_out);
}

// round 4
// speedup vs baseline: 1.0451x; 1.0451x over previous
#include <cuda_runtime.h>
#include <math.h>

#define F_IN 34
#define HID 256
#define NHEAD 8
#define HD 32
#define NLAYER 5
#define NMAX 50000
#define EMAX 800000
#define GMAX 2000
#define CHUNK 64

// ---------------- scratch (static __device__, no allocation) ----------------
__device__ float g_h[NMAX * HID];
__device__ float g_big[NMAX * 1024];   // GAT xl|xr [N,512] ; transformer q|k|v|skip [N,1024]
__device__ float g_t[NMAX * HID];      // temps
__device__ float g_wg[NLAYER * HID * 512];  // packed GAT weights (tf32-rounded)
__device__ float g_bg[NLAYER * 512];
__device__ float g_wt[HID * 1024];          // packed transformer weights (tf32-rounded)
__device__ float g_bt[1024];
__device__ float g_pool_sum[GMAX * HID];
__device__ float g_pool_max[GMAX * HID];
__device__ float g_cnt[GMAX];
__device__ float g_ge[GMAX * 2 * HID];
__device__ int g_deg[NMAX];
__device__ int g_rowptr[NMAX + 1];
__device__ int g_wptr[NMAX];
__device__ int g_csrc[EMAX];

// ---------------- helpers ----------------
__device__ __forceinline__ float gelu_f(float x) {
    return 0.5f * x * (1.0f + erff(x * 0.7071067811865475f));
}

__device__ __forceinline__ void atomicMaxFloat(float* addr, float value) {
    if (value >= 0.0f)
        atomicMax((int*)addr, __float_as_int(value));
    else
        atomicMin((unsigned int*)addr, __float_as_uint(value));
}

__device__ __forceinline__ float f2tf32_rna(float x) {
    unsigned r;
    asm("cvt.rna.tf32.f32 %0, %1;" : "=r"(r) : "f"(x));
    return __uint_as_float(r);
}

__device__ __forceinline__ void mma_tf32(float c[4], const unsigned a[4], unsigned b0, unsigned b1) {
    asm volatile(
        "mma.sync.aligned.m16n8k8.row.col.f32.tf32.tf32.f32 "
        "{%0,%1,%2,%3}, {%4,%5,%6,%7}, {%8,%9}, {%0,%1,%2,%3};"
        : "+f"(c[0]), "+f"(c[1]), "+f"(c[2]), "+f"(c[3])
        : "r"(a[0]), "r"(a[1]), "r"(a[2]), "r"(a[3]), "r"(b0), "r"(b1));
}

__device__ __forceinline__ void cp_async16(void* smem, const void* gmem, int src_bytes) {
    unsigned saddr = (unsigned)__cvta_generic_to_shared(smem);
    asm volatile("cp.async.cg.shared.global [%0], [%1], 16, %2;\n" ::"r"(saddr), "l"(gmem),
                 "r"(src_bytes));
}
__device__ __forceinline__ void cp_commit() { asm volatile("cp.async.commit_group;\n"); }
template <int Nw>
__device__ __forceinline__ void cp_wait() {
    asm volatile("cp.async.wait_group %0;\n" ::"n"(Nw));
}

// ---------------- weight packing (tf32-rounded) ----------------
__global__ void pack_gat_kernel(const float* __restrict__ Wl, const float* __restrict__ bl,
                                const float* __restrict__ Wr, const float* __restrict__ br) {
    int i = blockIdx.x * blockDim.x + threadIdx.x;
    if (i >= NLAYER * HID * 512) return;
    int l = i / (HID * 512);
    int r = (i / 512) % HID;
    int n = i % 512;
    float v = (n < HID) ? Wl[(l * HID + r) * HID + n] : Wr[(l * HID + r) * HID + n - HID];
    g_wg[i] = f2tf32_rna(v);
    if (r == 0) g_bg[l * 512 + n] = (n < HID) ? bl[l * HID + n] : br[l * HID + n - HID];
}

__global__ void pack_tr_kernel(const float* __restrict__ Wq, const float* __restrict__ bq,
                               const float* __restrict__ Wk, const float* __restrict__ bk,
                               const float* __restrict__ Wv, const float* __restrict__ bv,
                               const float* __restrict__ Ws, const float* __restrict__ bs) {
    int i = blockIdx.x * blockDim.x + threadIdx.x;
    if (i >= HID * 1024) return;
    int r = i / 1024;
    int n = i % 1024;
    int sel = n >> 8, cc = n & 255;
    const float* W = (sel == 0) ? Wq : (sel == 1) ? Wk : (sel == 2) ? Wv : Ws;
    const float* B = (sel == 0) ? bq : (sel == 1) ? bk : (sel == 2) ? bv : bs;
    g_wt[i] = f2tf32_rna(W[r * HID + cc]);
    if (r == 0) g_bt[n] = B[cc];
}

// ---------------- init ----------------
__global__ void init_kernel(int N, int G) {
    int i = blockIdx.x * blockDim.x + threadIdx.x;
    if (i < G * HID) {
        g_pool_sum[i] = 0.0f;
        g_pool_max[i] = -INFINITY;
    }
    if (i < G) g_cnt[i] = 0.0f;
    if (i < N) g_deg[i] = 0;
}

// ---------------- CSR build ----------------
__global__ void deg_kernel(const int* __restrict__ dst, int E) {
    int e = blockIdx.x * blockDim.x + threadIdx.x;
    if (e < E) atomicAdd(&g_deg[dst[e]], 1);
}

__global__ void scan_kernel(int N) {
    __shared__ int sdata[1024];
    __shared__ int carry;
    if (threadIdx.x == 0) carry = 0;
    __syncthreads();
    for (int base = 0; base < N; base += 1024) {
        int i = base + threadIdx.x;
        int v = (i < N) ? g_deg[i] : 0;
        sdata[threadIdx.x] = v;
        __syncthreads();
        for (int off = 1; off < 1024; off <<= 1) {
            int t = (threadIdx.x >= off) ? sdata[threadIdx.x - off] : 0;
            __syncthreads();
            sdata[threadIdx.x] += t;
            __syncthreads();
        }
        int incl = sdata[threadIdx.x];
        int excl = incl - v;
        if (i < N) {
            g_rowptr[i] = carry + excl;
            g_wptr[i] = carry + excl;
        }
        __syncthreads();
        if (threadIdx.x == 1023) carry += sdata[1023];
        __syncthreads();
    }
    if (threadIdx.x == 0) g_rowptr[N] = carry;
}

__global__ void scatter_kernel(const int* __restrict__ src, const int* __restrict__ dst, int E) {
    int e = blockIdx.x * blockDim.x + threadIdx.x;
    if (e >= E) return;
    int d = dst[e];
    int pos = atomicAdd(&g_wptr[d], 1);
    g_csrc[pos] = src[e];
}

// ---------------- fp32 SGEMM ----------------
#define BM 64
#define BN 64
#define BK 16
__global__ void gemm_bias_kernel(const float* __restrict__ A, const float* __restrict__ B,
                                 const float* __restrict__ bias, float* __restrict__ C,
                                 int M, int K, int Nc) {
    __shared__ float As[BK][BM + 1];
    __shared__ float Bs[BK][BN];
    int tid = threadIdx.x;
    int tx = tid & 15, ty = tid >> 4;
    int rowBase = blockIdx.y * BM;
    int colBase = blockIdx.x * BN;
    float acc[4][4];
#pragma unroll
    for (int i = 0; i < 4; i++)
#pragma unroll
        for (int j = 0; j < 4; j++) acc[i][j] = 0.0f;

    for (int k0 = 0; k0 < K; k0 += BK) {
#pragma unroll
        for (int it = 0; it < 4; it++) {
            int e = tid + it * 256;
            int kk = e % BK, mm = e / BK;
            int r = rowBase + mm, kz = k0 + kk;
            As[kk][mm] = (r < M && kz < K) ? A[(size_t)r * K + kz] : 0.0f;
        }
#pragma unroll
        for (int it = 0; it < 4; it++) {
            int e = tid + it * 256;
            int nn = e % BN, kk = e / BN;
            int kz = k0 + kk, cc = colBase + nn;
            Bs[kk][nn] = (kz < K && cc < Nc) ? B[(size_t)kz * Nc + cc] : 0.0f;
        }
        __syncthreads();
#pragma unroll
        for (int kk = 0; kk < BK; kk++) {
            float a[4], b[4];
#pragma unroll
            for (int i = 0; i < 4; i++) a[i] = As[kk][ty * 4 + i];
#pragma unroll
            for (int j = 0; j < 4; j++) b[j] = Bs[kk][tx * 4 + j];
#pragma unroll
            for (int i = 0; i < 4; i++)
#pragma unroll
                for (int j = 0; j < 4; j++) acc[i][j] += a[i] * b[j];
        }
        __syncthreads();
    }
#pragma unroll
    for (int i = 0; i < 4; i++) {
        int r = rowBase + ty * 4 + i;
        if (r >= M) continue;
#pragma unroll
        for (int j = 0; j < 4; j++) {
            int cc = colBase + tx * 4 + j;
            if (cc < Nc) C[(size_t)r * Nc + cc] = acc[i][j] + bias[cc];
        }
    }
}

// ---------------- tf32 tensor-core GEMM, cp.async 2-stage ----------------
#define TBM 128
#define TBN 128
#define TBK 16
#define A_LD 20
#define B_LD 136
__global__ __launch_bounds__(256) void gemm_tf32_kernel(
    const float* __restrict__ A, const float* __restrict__ B,
    const float* __restrict__ bias, float* __restrict__ C,
    int M, int K, int Nc) {
    __shared__ float As[2][TBM][A_LD];
    __shared__ float Bs[2][TBK][B_LD];

    int tid = threadIdx.x;
    int lane = tid & 31;
    int warp = tid >> 5;
    int warp_m = warp & 3;
    int warp_n = warp >> 2;
    int rowBase = blockIdx.y * TBM;
    int colBase = blockIdx.x * TBN;
    int kIters = K / TBK;

    float acc[2][8][4];
#pragma unroll
    for (int mt = 0; mt < 2; mt++)
#pragma unroll
        for (int nt = 0; nt < 8; nt++)
#pragma unroll
            for (int i = 0; i < 4; i++) acc[mt][nt][i] = 0.0f;

    auto issue = [&](int st, int it) {
        int k0 = it * TBK;
#pragma unroll
        for (int i = 0; i < 2; i++) {
            int q = tid + i * 256;
            int r = q >> 2, kq = q & 3;
            int gr = rowBase + r;
            int grc = (gr < M) ? gr : (M - 1);
            cp_async16(&As[st][r][kq * 4], A + (size_t)grc * K + k0 + kq * 4,
                       (gr < M) ? 16 : 0);
        }
#pragma unroll
        for (int i = 0; i < 2; i++) {
            int q = tid + i * 256;
            int kk = q >> 5, n4 = q & 31;
            cp_async16(&Bs[st][kk][n4 * 4], B + (size_t)(k0 + kk) * Nc + colBase + n4 * 4, 16);
        }
    };

    issue(0, 0);
    cp_commit();

    for (int it = 0; it < kIters; it++) {
        if (it + 1 < kIters) {
            issue((it + 1) & 1, it + 1);
            cp_commit();
            cp_wait<1>();
        } else {
            cp_wait<0>();
        }
        __syncthreads();
        int buf = it & 1;
#pragma unroll
        for (int ks = 0; ks < 2; ks++) {
            int kk = ks * 8;
            unsigned afr[2][4];
#pragma unroll
            for (int mt = 0; mt < 2; mt++) {
                int row = warp_m * 32 + mt * 16 + (lane >> 2);
                afr[mt][0] = __float_as_uint(As[buf][row][kk + (lane & 3)]);
                afr[mt][1] = __float_as_uint(As[buf][row + 8][kk + (lane & 3)]);
                afr[mt][2] = __float_as_uint(As[buf][row][kk + 4 + (lane & 3)]);
                afr[mt][3] = __float_as_uint(As[buf][row + 8][kk + 4 + (lane & 3)]);
            }
#pragma unroll
            for (int nt = 0; nt < 8; nt++) {
                int n = warp_n * 64 + nt * 8 + (lane >> 2);
                unsigned b0 = __float_as_uint(Bs[buf][kk + (lane & 3)][n]);
                unsigned b1 = __float_as_uint(Bs[buf][kk + 4 + (lane & 3)][n]);
                mma_tf32(acc[0][nt], afr[0], b0, b1);
                mma_tf32(acc[1][nt], afr[1], b0, b1);
            }
        }
        __syncthreads();
    }

#pragma unroll
    for (int mt = 0; mt < 2; mt++) {
#pragma unroll
        for (int half = 0; half < 2; half++) {
            int r = rowBase + warp_m * 32 + mt * 16 + (lane >> 2) + half * 8;
            if (r >= M) continue;
#pragma unroll
            for (int nt = 0; nt < 8; nt++) {
                int cc = colBase + warp_n * 64 + nt * 8 + 2 * (lane & 3);
                float2 v;
                v.x = acc[mt][nt][half * 2 + 0] + bias[cc];
                v.y = acc[mt][nt][half * 2 + 1] + bias[cc + 1];
                *(float2*)(C + (size_t)r * Nc + cc) = v;
            }
        }
    }
}

// ---------------- LayerNorm (+ optional GELU) ----------------
template <int DIM, bool ACT>
__global__ void ln_kernel(const float* __restrict__ in, const float* __restrict__ g,
                          const float* __restrict__ b, float* __restrict__ out) {
    int n = blockIdx.x, c = threadIdx.x;
    float v = in[n * DIM + c];
    __shared__ float sh[DIM];
    sh[c] = v;
    __syncthreads();
    for (int off = DIM / 2; off > 0; off >>= 1) {
        if (c < off) sh[c] += sh[c + off];
        __syncthreads();
    }
    float mean = sh[0] * (1.0f / DIM);
    __syncthreads();
    float d = v - mean;
    sh[c] = d * d;
    __syncthreads();
    for (int off = DIM / 2; off > 0; off >>= 1) {
        if (c < off) sh[c] += sh[c + off];
        __syncthreads();
    }
    float var = sh[0] * (1.0f / DIM);
    float y = d * rsqrtf(var + 1e-5f) * g[c] + b[c];
    if (ACT) y = gelu_f(y);
    out[n * DIM + c] = y;
}

// ---------------- GATv2: smem-staged srcs, 8-wide unconditional gathers ----------------
__global__ __launch_bounds__(256) void gat_kernel(
    const float* __restrict__ ab,  // [N,512]: xl | xr
    const float* __restrict__ att, const float* __restrict__ bias,
    const float* __restrict__ lng, const float* __restrict__ lnb,
    float* __restrict__ h) {
    int n = blockIdx.x;
    int c = threadIdx.x;
    __shared__ int s_src[CHUNK];
    __shared__ float sh[HID];

    float xr_c = ab[(size_t)n * 512 + 256 + c];
    float att_c = att[c];
    float m = -INFINITY, den = 0.0f, acc = 0.0f;
    int beg = g_rowptr[n];
    int cnt = g_rowptr[n + 1] - beg + 1;  // + self loop (last slot)

    for (int base = 0; base < cnt; base += CHUNK) {
        int len = min(CHUNK, cnt - base);
        if (c < len) {
            int idx = base + c;
            s_src[c] = (idx < cnt - 1) ? g_csrc[beg + idx] : n;
        }
        __syncthreads();
        for (int i = 0; i < len; i += 8) {
            int nu = len - i;  // >=1
            int srcs[8];
            float xlc[8], p[8];
#pragma unroll
            for (int u = 0; u < 8; u++) {
                int j = (u < nu) ? (i + u) : i;  // clamp to valid slot
                srcs[u] = s_src[j];
            }
#pragma unroll
            for (int u = 0; u < 8; u++)
                xlc[u] = __ldg(ab + (size_t)srcs[u] * 512 + c);  // unconditional: MLP=8
#pragma unroll
            for (int u = 0; u < 8; u++) {
                float t = xlc[u] + xr_c;
                t = (t > 0.0f) ? t : 0.2f * t;
                p[u] = t * att_c;
            }
#pragma unroll
            for (int o = 16; o > 0; o >>= 1) {
#pragma unroll
                for (int u = 0; u < 8; u++) p[u] += __shfl_xor_sync(0xffffffffu, p[u], o);
            }
#pragma unroll
            for (int u = 0; u < 8; u++) {
                float pv = (u < nu) ? p[u] : -INFINITY;
                float mn = fmaxf(m, pv);
                float sc = __expf(m - mn);
                float w = __expf(pv - mn);
                acc = acc * sc + w * xlc[u];
                den = den * sc + w;
                m = mn;
            }
        }
        __syncthreads();
    }

    float out = acc / (den + 1e-16f) + bias[c];
    sh[c] = out;
    __syncthreads();
    for (int off = HID / 2; off > 0; off >>= 1) {
        if (c < off) sh[c] += sh[c + off];
        __syncthreads();
    }
    float mean = sh[0] * (1.0f / HID);
    __syncthreads();
    float d = out - mean;
    sh[c] = d * d;
    __syncthreads();
    for (int off = HID / 2; off > 0; off >>= 1) {
        if (c < off) sh[c] += sh[c + off];
        __syncthreads();
    }
    float var = sh[0] * (1.0f / HID);
    float y = d * rsqrtf(var + 1e-5f) * lng[c] + lnb[c];
    h[(size_t)n * HID + c] += gelu_f(y);
}

// ---------------- TransformerConv: smem-staged srcs, 8-wide gathers ----------------
__global__ __launch_bounds__(256) void trans_kernel(
    const float* __restrict__ qkvs,  // [N,1024]: q|k|v|skip
    const float* __restrict__ lng, const float* __restrict__ lnb,
    float* __restrict__ h) {
    int n = blockIdx.x;
    int c = threadIdx.x;
    __shared__ int s_src[CHUNK];
    __shared__ float sh[HID];
    const float scale = 0.17677669529663687f;  // 1/sqrt(32)

    float q_c = qkvs[(size_t)n * 1024 + c];
    float m = -INFINITY, den = 0.0f, acc = 0.0f;
    int beg = g_rowptr[n];
    int cnt = g_rowptr[n + 1] - beg;  // no self loops

    for (int base = 0; base < cnt; base += CHUNK) {
        int len = min(CHUNK, cnt - base);
        if (c < len) s_src[c] = g_csrc[beg + base + c];
        __syncthreads();
        for (int i = 0; i < len; i += 8) {
            int nu = len - i;
            int srcs[8];
            float kc[8], vc[8], p[8];
#pragma unroll
            for (int u = 0; u < 8; u++) {
                int j = (u < nu) ? (i + u) : i;
                srcs[u] = s_src[j];
            }
#pragma unroll
            for (int u = 0; u < 8; u++) {
                const float* row = qkvs + (size_t)srcs[u] * 1024;
                kc[u] = __ldg(row + 256 + c);
                vc[u] = __ldg(row + 512 + c);
            }
#pragma unroll
            for (int u = 0; u < 8; u++) p[u] = q_c * kc[u];
#pragma unroll
            for (int o = 16; o > 0; o >>= 1) {
#pragma unroll
                for (int u = 0; u < 8; u++) p[u] += __shfl_xor_sync(0xffffffffu, p[u], o);
            }
#pragma unroll
            for (int u = 0; u < 8; u++) {
                float pv = (u < nu) ? p[u] * scale : -INFINITY;
                float mn = fmaxf(m, pv);
                float sc = __expf(m - mn);
                float w = __expf(pv - mn);
                acc = acc * sc + w * vc[u];
                den = den * sc + w;
                m = mn;
            }
        }
        __syncthreads();
    }

    float out = acc / (den + 1e-16f) + qkvs[(size_t)n * 1024 + 768 + c];
    sh[c] = out;
    __syncthreads();
    for (int off = HID / 2; off > 0; off >>= 1) {
        if (c < off) sh[c] += sh[c + off];
        __syncthreads();
    }
    float mean = sh[0] * (1.0f / HID);
    __syncthreads();
    float d = out - mean;
    sh[c] = d * d;
    __syncthreads();
    for (int off = HID / 2; off > 0; off >>= 1) {
        if (c < off) sh[c] += sh[c + off];
        __syncthreads();
    }
    float var = sh[0] * (1.0f / HID);
    float y = d * rsqrtf(var + 1e-5f) * lng[c] + lnb[c];
    h[(size_t)n * HID + c] += y;
}

// ---------------- pooling ----------------
__global__ void pool_kernel(const float* __restrict__ h, const int* __restrict__ batch) {
    int n = blockIdx.x, c = threadIdx.x;
    int g = batch[n];
    float v = h[(size_t)n * HID + c];
    atomicAdd(&g_pool_sum[g * HID + c], v);
    atomicMaxFloat(&g_pool_max[g * HID + c], v);
    if (c == 0) atomicAdd(&g_cnt[g], 1.0f);
}

__global__ void finalize_kernel(int G) {
    int i = blockIdx.x * blockDim.x + threadIdx.x;
    if (i >= G * 2 * HID) return;
    int g = i / (2 * HID), c = i % (2 * HID);
    float v;
    if (c < HID) {
        v = g_pool_sum[g * HID + c] / fmaxf(g_cnt[g], 1.0f);
    } else {
        v = g_pool_max[g * HID + (c - HID)];
        if (!isfinite(v)) v = 0.0f;
    }
    g_ge[i] = v;
}

// ---------------- launch ----------------
static void run_gemm_f32(const float* A, const float* B, const float* bias, float* C,
                         int M, int K, int Nc) {
    dim3 grid((Nc + BN - 1) / BN, (M + BM - 1) / BM);
    gemm_bias_kernel<<<grid, 256>>>(A, B, bias, C, M, K, Nc);
}

static void run_gemm_tc(const float* A, const float* B, const float* bias, float* C,
                        int M, int K, int Nc) {
    dim3 grid(Nc / TBN, (M + TBM - 1) / TBM);
    gemm_tf32_kernel<<<grid, 256>>>(A, B, bias, C, M, K, Nc);
}

extern "C" void kernel_launch(void* const* d_in, const int* in_sizes, int n_in,
                              void* d_out, int out_size) {
    const float* x = (const float*)d_in[0];
    const int* ei = (const int*)d_in[1];
    const int* batch = (const int*)d_in[2];
    const float* in_W = (const float*)d_in[3];
    const float* in_b = (const float*)d_in[4];
    const float* in_ln_g = (const float*)d_in[5];
    const float* in_ln_b = (const float*)d_in[6];
    const float* gat_Wl = (const float*)d_in[7];
    const float* gat_bl = (const float*)d_in[8];
    const float* gat_Wr = (const float*)d_in[9];
    const float* gat_br = (const float*)d_in[10];
    const float* gat_att = (const float*)d_in[11];
    const float* gat_bias = (const float*)d_in[12];
    const float* gat_ln_g = (const float*)d_in[13];
    const float* gat_ln_b = (const float*)d_in[14];
    const float* tr_Wq = (const float*)d_in[15];
    const float* tr_bq = (const float*)d_in[16];
    const float* tr_Wk = (const float*)d_in[17];
    const float* tr_bk = (const float*)d_in[18];
    const float* tr_Wv = (const float*)d_in[19];
    const float* tr_bv = (const float*)d_in[20];
    const float* tr_Wskip = (const float*)d_in[21];
    const float* tr_bskip = (const float*)d_in[22];
    const float* tr_ln_g = (const float*)d_in[23];
    const float* tr_ln_b = (const float*)d_in[24];
    const float* out_W = (const float*)d_in[25];
    const float* out_b = (const float*)d_in[26];
    const float* out_ln_g = (const float*)d_in[27];
    const float* out_ln_b = (const float*)d_in[28];

    int N = in_sizes[0] / F_IN;
    int E = in_sizes[1] / 2;
    int G = out_size / (2 * HID);
    const int* src = ei;
    const int* dst = ei + E;

    float *hP, *bigP, *tP, *geP, *wgP, *bgP, *wtP, *btP;
    cudaGetSymbolAddress((void**)&hP, g_h);
    cudaGetSymbolAddress((void**)&bigP, g_big);
    cudaGetSymbolAddress((void**)&tP, g_t);
    cudaGetSymbolAddress((void**)&geP, g_ge);
    cudaGetSymbolAddress((void**)&wgP, g_wg);
    cudaGetSymbolAddress((void**)&bgP, g_bg);
    cudaGetSymbolAddress((void**)&wtP, g_wt);
    cudaGetSymbolAddress((void**)&btP, g_bt);

    // 0: pack GAT weights
    pack_gat_kernel<<<(NLAYER * HID * 512 + 255) / 256, 256>>>(gat_Wl, gat_bl, gat_Wr, gat_br);
    // 1-2: input embed (K=34, fp32)
    run_gemm_f32(x, in_W, in_b, tP, N, F_IN, HID);
    ln_kernel<HID, true><<<N, HID>>>(tP, in_ln_g, in_ln_b, hP);
    // 3: first GAT GEMM (profiled launch slot)
    run_gemm_tc(hP, wgP, bgP, bigP, N, HID, 512);
    // 4: init pools/deg
    int initN = (G * HID > N) ? G * HID : N;
    init_kernel<<<(initN + 255) / 256, 256>>>(N, G);
    // 5-7: build CSR by destination
    deg_kernel<<<(E + 255) / 256, 256>>>(dst, E);
    scan_kernel<<<1, 1024>>>(N);
    scatter_kernel<<<(E + 255) / 256, 256>>>(src, dst, E);
    // 8: GAT layer 0 aggregate
    gat_kernel<<<N, HID>>>(bigP, gat_att, gat_bias, gat_ln_g, gat_ln_b, hP);
    // layers 1..4
    for (int l = 1; l < NLAYER; l++) {
        run_gemm_tc(hP, wgP + (size_t)l * HID * 512, bgP + (size_t)l * 512, bigP, N, HID, 512);
        gat_kernel<<<N, HID>>>(bigP, gat_att + (size_t)l * HID, gat_bias + (size_t)l * HID,
                               gat_ln_g + (size_t)l * HID, gat_ln_b + (size_t)l * HID, hP);
    }

    // TransformerConv: one packed GEMM -> q|k|v|skip
    pack_tr_kernel<<<(HID * 1024 + 255) / 256, 256>>>(tr_Wq, tr_bq, tr_Wk, tr_bk, tr_Wv, tr_bv,
                                                      tr_Wskip, tr_bskip);
    run_gemm_tc(hP, wtP, btP, bigP, N, HID, 1024);
    trans_kernel<<<N, HID>>>(bigP, tr_ln_g, tr_ln_b, hP);

    // pooling
    pool_kernel<<<N, HID>>>(hP, batch);
    finalize_kernel<<<(G * 2 * HID + 255) / 256, 256>>>(G);

    // output projection (fp32) + LN + GELU
    run_gemm_f32(geP, out_W, out_b, tP, G, 2 * HID, 2 * HID);
    ln_kernel<2 * HID, true><<<G, 2 * HID>>>(tP, out_ln_g, out_ln_b, (float*)d_out);
}

// round 5
// speedup vs baseline: 1.9454x; 1.8614x over previous
#include <cuda_runtime.h>
#include <math.h>

#define F_IN 34
#define HID 256
#define NHEAD 8
#define HD 32
#define NLAYER 5
#define NMAX 50000
#define EMAX 800000
#define GMAX 2000
#define CHUNK 64

// ---------------- scratch (static __device__, no allocation) ----------------
__device__ float g_h[NMAX * HID];
__device__ float g_big[NMAX * 1024];   // GAT xl|xr [N,512] ; transformer q|k|v|skip [N,1024]
__device__ float g_t[NMAX * HID];      // temps
__device__ float g_wg[NLAYER * HID * 512];  // packed GAT weights (tf32-rounded)
__device__ float g_bg[NLAYER * 512];
__device__ float g_wt[HID * 1024];          // packed transformer weights (tf32-rounded)
__device__ float g_bt[1024];
__device__ float g_pool_sum[GMAX * HID];
__device__ float g_pool_max[GMAX * HID];
__device__ float g_cnt[GMAX];
__device__ float g_ge[GMAX * 2 * HID];
__device__ int g_deg[NMAX];
__device__ int g_rowptr[NMAX + 1];
__device__ int g_wptr[NMAX];
__device__ int g_csrc[EMAX];

// ---------------- helpers ----------------
__device__ __forceinline__ float gelu_f(float x) {
    return 0.5f * x * (1.0f + erff(x * 0.7071067811865475f));
}

__device__ __forceinline__ void atomicMaxFloat(float* addr, float value) {
    if (value >= 0.0f)
        atomicMax((int*)addr, __float_as_int(value));
    else
        atomicMin((unsigned int*)addr, __float_as_uint(value));
}

__device__ __forceinline__ float f2tf32_rna(float x) {
    unsigned r;
    asm("cvt.rna.tf32.f32 %0, %1;" : "=r"(r) : "f"(x));
    return __uint_as_float(r);
}

__device__ __forceinline__ float lrelu(float x) { return (x > 0.0f) ? x : 0.2f * x; }

__device__ __forceinline__ void mma_tf32(float c[4], const unsigned a[4], unsigned b0, unsigned b1) {
    asm volatile(
        "mma.sync.aligned.m16n8k8.row.col.f32.tf32.tf32.f32 "
        "{%0,%1,%2,%3}, {%4,%5,%6,%7}, {%8,%9}, {%0,%1,%2,%3};"
        : "+f"(c[0]), "+f"(c[1]), "+f"(c[2]), "+f"(c[3])
        : "r"(a[0]), "r"(a[1]), "r"(a[2]), "r"(a[3]), "r"(b0), "r"(b1));
}

__device__ __forceinline__ void cp_async16(void* smem, const void* gmem, int src_bytes) {
    unsigned saddr = (unsigned)__cvta_generic_to_shared(smem);
    asm volatile("cp.async.cg.shared.global [%0], [%1], 16, %2;\n" ::"r"(saddr), "l"(gmem),
                 "r"(src_bytes));
}
__device__ __forceinline__ void cp_commit() { asm volatile("cp.async.commit_group;\n"); }
template <int Nw>
__device__ __forceinline__ void cp_wait() {
    asm volatile("cp.async.wait_group %0;\n" ::"n"(Nw));
}

// ---------------- weight packing (tf32-rounded) ----------------
__global__ void pack_gat_kernel(const float* __restrict__ Wl, const float* __restrict__ bl,
                                const float* __restrict__ Wr, const float* __restrict__ br) {
    int i = blockIdx.x * blockDim.x + threadIdx.x;
    if (i >= NLAYER * HID * 512) return;
    int l = i / (HID * 512);
    int r = (i / 512) % HID;
    int n = i % 512;
    float v = (n < HID) ? Wl[(l * HID + r) * HID + n] : Wr[(l * HID + r) * HID + n - HID];
    g_wg[i] = f2tf32_rna(v);
    if (r == 0) g_bg[l * 512 + n] = (n < HID) ? bl[l * HID + n] : br[l * HID + n - HID];
}

__global__ void pack_tr_kernel(const float* __restrict__ Wq, const float* __restrict__ bq,
                               const float* __restrict__ Wk, const float* __restrict__ bk,
                               const float* __restrict__ Wv, const float* __restrict__ bv,
                               const float* __restrict__ Ws, const float* __restrict__ bs) {
    int i = blockIdx.x * blockDim.x + threadIdx.x;
    if (i >= HID * 1024) return;
    int r = i / 1024;
    int n = i % 1024;
    int sel = n >> 8, cc = n & 255;
    const float* W = (sel == 0) ? Wq : (sel == 1) ? Wk : (sel == 2) ? Wv : Ws;
    const float* B = (sel == 0) ? bq : (sel == 1) ? bk : (sel == 2) ? bv : bs;
    g_wt[i] = f2tf32_rna(W[r * HID + cc]);
    if (r == 0) g_bt[n] = B[cc];
}

// ---------------- init ----------------
__global__ void init_kernel(int N, int G) {
    int i = blockIdx.x * blockDim.x + threadIdx.x;
    if (i < G * HID) {
        g_pool_sum[i] = 0.0f;
        g_pool_max[i] = -INFINITY;
    }
    if (i < G) g_cnt[i] = 0.0f;
    if (i < N) g_deg[i] = 0;
}

// ---------------- CSR build ----------------
__global__ void deg_kernel(const int* __restrict__ dst, int E) {
    int e = blockIdx.x * blockDim.x + threadIdx.x;
    if (e < E) atomicAdd(&g_deg[dst[e]], 1);
}

__global__ void scan_kernel(int N) {
    __shared__ int sdata[1024];
    __shared__ int carry;
    if (threadIdx.x == 0) carry = 0;
    __syncthreads();
    for (int base = 0; base < N; base += 1024) {
        int i = base + threadIdx.x;
        int v = (i < N) ? g_deg[i] : 0;
        sdata[threadIdx.x] = v;
        __syncthreads();
        for (int off = 1; off < 1024; off <<= 1) {
            int t = (threadIdx.x >= off) ? sdata[threadIdx.x - off] : 0;
            __syncthreads();
            sdata[threadIdx.x] += t;
            __syncthreads();
        }
        int incl = sdata[threadIdx.x];
        int excl = incl - v;
        if (i < N) {
            g_rowptr[i] = carry + excl;
            g_wptr[i] = carry + excl;
        }
        __syncthreads();
        if (threadIdx.x == 1023) carry += sdata[1023];
        __syncthreads();
    }
    if (threadIdx.x == 0) g_rowptr[N] = carry;
}

__global__ void scatter_kernel(const int* __restrict__ src, const int* __restrict__ dst, int E) {
    int e = blockIdx.x * blockDim.x + threadIdx.x;
    if (e >= E) return;
    int d = dst[e];
    int pos = atomicAdd(&g_wptr[d], 1);
    g_csrc[pos] = src[e];
}

// ---------------- fp32 SGEMM ----------------
#define BM 64
#define BN 64
#define BK 16
__global__ void gemm_bias_kernel(const float* __restrict__ A, const float* __restrict__ B,
                                 const float* __restrict__ bias, float* __restrict__ C,
                                 int M, int K, int Nc) {
    __shared__ float As[BK][BM + 1];
    __shared__ float Bs[BK][BN];
    int tid = threadIdx.x;
    int tx = tid & 15, ty = tid >> 4;
    int rowBase = blockIdx.y * BM;
    int colBase = blockIdx.x * BN;
    float acc[4][4];
#pragma unroll
    for (int i = 0; i < 4; i++)
#pragma unroll
        for (int j = 0; j < 4; j++) acc[i][j] = 0.0f;

    for (int k0 = 0; k0 < K; k0 += BK) {
#pragma unroll
        for (int it = 0; it < 4; it++) {
            int e = tid + it * 256;
            int kk = e % BK, mm = e / BK;
            int r = rowBase + mm, kz = k0 + kk;
            As[kk][mm] = (r < M && kz < K) ? A[(size_t)r * K + kz] : 0.0f;
        }
#pragma unroll
        for (int it = 0; it < 4; it++) {
            int e = tid + it * 256;
            int nn = e % BN, kk = e / BN;
            int kz = k0 + kk, cc = colBase + nn;
            Bs[kk][nn] = (kz < K && cc < Nc) ? B[(size_t)kz * Nc + cc] : 0.0f;
        }
        __syncthreads();
#pragma unroll
        for (int kk = 0; kk < BK; kk++) {
            float a[4], b[4];
#pragma unroll
            for (int i = 0; i < 4; i++) a[i] = As[kk][ty * 4 + i];
#pragma unroll
            for (int j = 0; j < 4; j++) b[j] = Bs[kk][tx * 4 + j];
#pragma unroll
            for (int i = 0; i < 4; i++)
#pragma unroll
                for (int j = 0; j < 4; j++) acc[i][j] += a[i] * b[j];
        }
        __syncthreads();
    }
#pragma unroll
    for (int i = 0; i < 4; i++) {
        int r = rowBase + ty * 4 + i;
        if (r >= M) continue;
#pragma unroll
        for (int j = 0; j < 4; j++) {
            int cc = colBase + tx * 4 + j;
            if (cc < Nc) C[(size_t)r * Nc + cc] = acc[i][j] + bias[cc];
        }
    }
}

// ---------------- tf32 tensor-core GEMM, cp.async 2-stage ----------------
#define TBM 128
#define TBN 128
#define TBK 16
#define A_LD 20
#define B_LD 136
__global__ __launch_bounds__(256) void gemm_tf32_kernel(
    const float* __restrict__ A, const float* __restrict__ B,
    const float* __restrict__ bias, float* __restrict__ C,
    int M, int K, int Nc) {
    __shared__ float As[2][TBM][A_LD];
    __shared__ float Bs[2][TBK][B_LD];

    int tid = threadIdx.x;
    int lane = tid & 31;
    int warp = tid >> 5;
    int warp_m = warp & 3;
    int warp_n = warp >> 2;
    int rowBase = blockIdx.y * TBM;
    int colBase = blockIdx.x * TBN;
    int kIters = K / TBK;

    float acc[2][8][4];
#pragma unroll
    for (int mt = 0; mt < 2; mt++)
#pragma unroll
        for (int nt = 0; nt < 8; nt++)
#pragma unroll
            for (int i = 0; i < 4; i++) acc[mt][nt][i] = 0.0f;

    auto issue = [&](int st, int it) {
        int k0 = it * TBK;
#pragma unroll
        for (int i = 0; i < 2; i++) {
            int q = tid + i * 256;
            int r = q >> 2, kq = q & 3;
            int gr = rowBase + r;
            int grc = (gr < M) ? gr : (M - 1);
            cp_async16(&As[st][r][kq * 4], A + (size_t)grc * K + k0 + kq * 4,
                       (gr < M) ? 16 : 0);
        }
#pragma unroll
        for (int i = 0; i < 2; i++) {
            int q = tid + i * 256;
            int kk = q >> 5, n4 = q & 31;
            cp_async16(&Bs[st][kk][n4 * 4], B + (size_t)(k0 + kk) * Nc + colBase + n4 * 4, 16);
        }
    };

    issue(0, 0);
    cp_commit();

    for (int it = 0; it < kIters; it++) {
        if (it + 1 < kIters) {
            issue((it + 1) & 1, it + 1);
            cp_commit();
            cp_wait<1>();
        } else {
            cp_wait<0>();
        }
        __syncthreads();
        int buf = it & 1;
#pragma unroll
        for (int ks = 0; ks < 2; ks++) {
            int kk = ks * 8;
            unsigned afr[2][4];
#pragma unroll
            for (int mt = 0; mt < 2; mt++) {
                int row = warp_m * 32 + mt * 16 + (lane >> 2);
                afr[mt][0] = __float_as_uint(As[buf][row][kk + (lane & 3)]);
                afr[mt][1] = __float_as_uint(As[buf][row + 8][kk + (lane & 3)]);
                afr[mt][2] = __float_as_uint(As[buf][row][kk + 4 + (lane & 3)]);
                afr[mt][3] = __float_as_uint(As[buf][row + 8][kk + 4 + (lane & 3)]);
            }
#pragma unroll
            for (int nt = 0; nt < 8; nt++) {
                int n = warp_n * 64 + nt * 8 + (lane >> 2);
                unsigned b0 = __float_as_uint(Bs[buf][kk + (lane & 3)][n]);
                unsigned b1 = __float_as_uint(Bs[buf][kk + 4 + (lane & 3)][n]);
                mma_tf32(acc[0][nt], afr[0], b0, b1);
                mma_tf32(acc[1][nt], afr[1], b0, b1);
            }
        }
        __syncthreads();
    }

#pragma unroll
    for (int mt = 0; mt < 2; mt++) {
#pragma unroll
        for (int half = 0; half < 2; half++) {
            int r = rowBase + warp_m * 32 + mt * 16 + (lane >> 2) + half * 8;
            if (r >= M) continue;
#pragma unroll
            for (int nt = 0; nt < 8; nt++) {
                int cc = colBase + warp_n * 64 + nt * 8 + 2 * (lane & 3);
                float2 v;
                v.x = acc[mt][nt][half * 2 + 0] + bias[cc];
                v.y = acc[mt][nt][half * 2 + 1] + bias[cc + 1];
                *(float2*)(C + (size_t)r * Nc + cc) = v;
            }
        }
    }
}

// ---------------- LayerNorm (+ optional GELU) ----------------
template <int DIM, bool ACT>
__global__ void ln_kernel(const float* __restrict__ in, const float* __restrict__ g,
                          const float* __restrict__ b, float* __restrict__ out) {
    int n = blockIdx.x, c = threadIdx.x;
    float v = in[n * DIM + c];
    __shared__ float sh[DIM];
    sh[c] = v;
    __syncthreads();
    for (int off = DIM / 2; off > 0; off >>= 1) {
        if (c < off) sh[c] += sh[c + off];
        __syncthreads();
    }
    float mean = sh[0] * (1.0f / DIM);
    __syncthreads();
    float d = v - mean;
    sh[c] = d * d;
    __syncthreads();
    for (int off = DIM / 2; off > 0; off >>= 1) {
        if (c < off) sh[c] += sh[c + off];
        __syncthreads();
    }
    float var = sh[0] * (1.0f / DIM);
    float y = d * rsqrtf(var + 1e-5f) * g[c] + b[c];
    if (ACT) y = gelu_f(y);
    out[n * DIM + c] = y;
}

// ---------------- GATv2: 64 threads/block, float4/thread, octet-reduce, batched-max softmax ----
__global__ __launch_bounds__(64) void gat_kernel(
    const float* __restrict__ ab,  // [N,512]: xl | xr
    const float* __restrict__ att, const float* __restrict__ bias,
    const float* __restrict__ lng, const float* __restrict__ lnb,
    float* __restrict__ h) {
    int n = blockIdx.x;
    int t = threadIdx.x;  // 0..63 ; channels 4t..4t+3 ; head = t/8
    int lane = t & 31, warp = t >> 5;
    int c4 = t * 4;
    __shared__ int s_src[CHUNK];
    __shared__ float s_red[2];

    float4 xr4 = *(const float4*)(ab + (size_t)n * 512 + 256 + c4);
    float4 at4 = *(const float4*)(att + c4);
    float m = -INFINITY, den = 0.0f;
    float4 acc = make_float4(0.f, 0.f, 0.f, 0.f);
    int beg = g_rowptr[n];
    int cnt = g_rowptr[n + 1] - beg + 1;  // + self loop (last slot)

    for (int base = 0; base < cnt; base += CHUNK) {
        int len = min(CHUNK, cnt - base);
        if (t < len) {
            int idx = base + t;
            s_src[t] = (idx < cnt - 1) ? g_csrc[beg + idx] : n;
        }
        __syncthreads();
        for (int i = 0; i < len; i += 4) {
            int nu = len - i;
            int srcs[4];
            float4 xl4[4];
            float p[4];
#pragma unroll
            for (int u = 0; u < 4; u++) srcs[u] = s_src[(u < nu) ? (i + u) : i];
#pragma unroll
            for (int u = 0; u < 4; u++)
                xl4[u] = __ldg((const float4*)(ab + (size_t)srcs[u] * 512 + c4));
#pragma unroll
            for (int u = 0; u < 4; u++) {
                p[u] = lrelu(xl4[u].x + xr4.x) * at4.x + lrelu(xl4[u].y + xr4.y) * at4.y +
                       lrelu(xl4[u].z + xr4.z) * at4.z + lrelu(xl4[u].w + xr4.w) * at4.w;
            }
            // octet butterfly: head dot replicated across its 8 lanes
#pragma unroll
            for (int o = 4; o > 0; o >>= 1) {
#pragma unroll
                for (int u = 0; u < 4; u++) p[u] += __shfl_xor_sync(0xffffffffu, p[u], o);
            }
#pragma unroll
            for (int u = 0; u < 4; u++)
                if (u >= nu) p[u] = -INFINITY;
            float mx = fmaxf(fmaxf(p[0], p[1]), fmaxf(p[2], p[3]));
            float mn = fmaxf(m, mx);
            float sc = __expf(m - mn);  // m=-INF first time -> 0, mn always finite
            acc.x *= sc; acc.y *= sc; acc.z *= sc; acc.w *= sc;
            den *= sc;
#pragma unroll
            for (int u = 0; u < 4; u++) {
                float w = __expf(p[u] - mn);
                den += w;
                acc.x += w * xl4[u].x;
                acc.y += w * xl4[u].y;
                acc.z += w * xl4[u].z;
                acc.w += w * xl4[u].w;
            }
            m = mn;
        }
        __syncthreads();
    }

    float inv = 1.0f / (den + 1e-16f);
    float4 b4 = *(const float4*)(bias + c4);
    float o0 = acc.x * inv + b4.x;
    float o1 = acc.y * inv + b4.y;
    float o2 = acc.z * inv + b4.z;
    float o3 = acc.w * inv + b4.w;
    // LN over 256 channels: warp reduce + 2-warp combine
    float s = o0 + o1 + o2 + o3;
#pragma unroll
    for (int o = 16; o > 0; o >>= 1) s += __shfl_xor_sync(0xffffffffu, s, o);
    if (lane == 0) s_red[warp] = s;
    __syncthreads();
    float mean = (s_red[0] + s_red[1]) * (1.0f / HID);
    float d0 = o0 - mean, d1 = o1 - mean, d2 = o2 - mean, d3 = o3 - mean;
    float ss = d0 * d0 + d1 * d1 + d2 * d2 + d3 * d3;
#pragma unroll
    for (int o = 16; o > 0; o >>= 1) ss += __shfl_xor_sync(0xffffffffu, ss, o);
    __syncthreads();
    if (lane == 0) s_red[warp] = ss;
    __syncthreads();
    float var = (s_red[0] + s_red[1]) * (1.0f / HID);
    float r = rsqrtf(var + 1e-5f);
    float4 g4 = *(const float4*)(lng + c4);
    float4 lb4 = *(const float4*)(lnb + c4);
    float4 hv = *(float4*)(h + (size_t)n * HID + c4);
    hv.x += gelu_f(d0 * r * g4.x + lb4.x);
    hv.y += gelu_f(d1 * r * g4.y + lb4.y);
    hv.z += gelu_f(d2 * r * g4.z + lb4.z);
    hv.w += gelu_f(d3 * r * g4.w + lb4.w);
    *(float4*)(h + (size_t)n * HID + c4) = hv;
}

// ---------------- TransformerConv: 64 threads/block, float4/thread ----------------
__global__ __launch_bounds__(64) void trans_kernel(
    const float* __restrict__ qkvs,  // [N,1024]: q|k|v|skip
    const float* __restrict__ lng, const float* __restrict__ lnb,
    float* __restrict__ h) {
    int n = blockIdx.x;
    int t = threadIdx.x;
    int lane = t & 31, warp = t >> 5;
    int c4 = t * 4;
    __shared__ int s_src[CHUNK];
    __shared__ float s_red[2];
    const float scale = 0.17677669529663687f;  // 1/sqrt(32)

    float4 q4 = *(const float4*)(qkvs + (size_t)n * 1024 + c4);
    float m = -INFINITY, den = 0.0f;
    float4 acc = make_float4(0.f, 0.f, 0.f, 0.f);
    int beg = g_rowptr[n];
    int cnt = g_rowptr[n + 1] - beg;  // no self loops

    for (int base = 0; base < cnt; base += CHUNK) {
        int len = min(CHUNK, cnt - base);
        if (t < len) s_src[t] = g_csrc[beg + base + t];
        __syncthreads();
        for (int i = 0; i < len; i += 4) {
            int nu = len - i;
            int srcs[4];
            float4 k4[4], v4[4];
            float p[4];
#pragma unroll
            for (int u = 0; u < 4; u++) srcs[u] = s_src[(u < nu) ? (i + u) : i];
#pragma unroll
            for (int u = 0; u < 4; u++) {
                const float* row = qkvs + (size_t)srcs[u] * 1024;
                k4[u] = __ldg((const float4*)(row + 256 + c4));
                v4[u] = __ldg((const float4*)(row + 512 + c4));
            }
#pragma unroll
            for (int u = 0; u < 4; u++)
                p[u] = q4.x * k4[u].x + q4.y * k4[u].y + q4.z * k4[u].z + q4.w * k4[u].w;
#pragma unroll
            for (int o = 4; o > 0; o >>= 1) {
#pragma unroll
                for (int u = 0; u < 4; u++) p[u] += __shfl_xor_sync(0xffffffffu, p[u], o);
            }
#pragma unroll
            for (int u = 0; u < 4; u++) p[u] = (u < nu) ? p[u] * scale : -INFINITY;
            float mx = fmaxf(fmaxf(p[0], p[1]), fmaxf(p[2], p[3]));
            float mn = fmaxf(m, mx);
            float sc = __expf(m - mn);
            acc.x *= sc; acc.y *= sc; acc.z *= sc; acc.w *= sc;
            den *= sc;
#pragma unroll
            for (int u = 0; u < 4; u++) {
                float w = __expf(p[u] - mn);
                den += w;
                acc.x += w * v4[u].x;
                acc.y += w * v4[u].y;
                acc.z += w * v4[u].z;
                acc.w += w * v4[u].w;
            }
            m = mn;
        }
        __syncthreads();
    }

    float inv = 1.0f / (den + 1e-16f);
    const float* skip = qkvs + (size_t)n * 1024 + 768;
    float4 sk4 = *(const float4*)(skip + c4);
    float o0 = acc.x * inv + sk4.x;
    float o1 = acc.y * inv + sk4.y;
    float o2 = acc.z * inv + sk4.z;
    float o3 = acc.w * inv + sk4.w;
    float s = o0 + o1 + o2 + o3;
#pragma unroll
    for (int o = 16; o > 0; o >>= 1) s += __shfl_xor_sync(0xffffffffu, s, o);
    if (lane == 0) s_red[warp] = s;
    __syncthreads();
    float mean = (s_red[0] + s_red[1]) * (1.0f / HID);
    float d0 = o0 - mean, d1 = o1 - mean, d2 = o2 - mean, d3 = o3 - mean;
    float ss = d0 * d0 + d1 * d1 + d2 * d2 + d3 * d3;
#pragma unroll
    for (int o = 16; o > 0; o >>= 1) ss += __shfl_xor_sync(0xffffffffu, ss, o);
    __syncthreads();
    if (lane == 0) s_red[warp] = ss;
    __syncthreads();
    float var = (s_red[0] + s_red[1]) * (1.0f / HID);
    float r = rsqrtf(var + 1e-5f);
    float4 g4 = *(const float4*)(lng + c4);
    float4 lb4 = *(const float4*)(lnb + c4);
    float4 hv = *(float4*)(h + (size_t)n * HID + c4);
    hv.x += d0 * r * g4.x + lb4.x;
    hv.y += d1 * r * g4.y + lb4.y;
    hv.z += d2 * r * g4.z + lb4.z;
    hv.w += d3 * r * g4.w + lb4.w;
    *(float4*)(h + (size_t)n * HID + c4) = hv;
}

// ---------------- pooling ----------------
__global__ void pool_kernel(const float* __restrict__ h, const int* __restrict__ batch) {
    int n = blockIdx.x, c = threadIdx.x;
    int g = batch[n];
    float v = h[(size_t)n * HID + c];
    atomicAdd(&g_pool_sum[g * HID + c], v);
    atomicMaxFloat(&g_pool_max[g * HID + c], v);
    if (c == 0) atomicAdd(&g_cnt[g], 1.0f);
}

__global__ void finalize_kernel(int G) {
    int i = blockIdx.x * blockDim.x + threadIdx.x;
    if (i >= G * 2 * HID) return;
    int g = i / (2 * HID), c = i % (2 * HID);
    float v;
    if (c < HID) {
        v = g_pool_sum[g * HID + c] / fmaxf(g_cnt[g], 1.0f);
    } else {
        v = g_pool_max[g * HID + (c - HID)];
        if (!isfinite(v)) v = 0.0f;
    }
    g_ge[i] = v;
}

// ---------------- launch ----------------
static void run_gemm_f32(const float* A, const float* B, const float* bias, float* C,
                         int M, int K, int Nc) {
    dim3 grid((Nc + BN - 1) / BN, (M + BM - 1) / BM);
    gemm_bias_kernel<<<grid, 256>>>(A, B, bias, C, M, K, Nc);
}

static void run_gemm_tc(const float* A, const float* B, const float* bias, float* C,
                        int M, int K, int Nc) {
    dim3 grid(Nc / TBN, (M + TBM - 1) / TBM);
    gemm_tf32_kernel<<<grid, 256>>>(A, B, bias, C, M, K, Nc);
}

extern "C" void kernel_launch(void* const* d_in, const int* in_sizes, int n_in,
                              void* d_out, int out_size) {
    const float* x = (const float*)d_in[0];
    const int* ei = (const int*)d_in[1];
    const int* batch = (const int*)d_in[2];
    const float* in_W = (const float*)d_in[3];
    const float* in_b = (const float*)d_in[4];
    const float* in_ln_g = (const float*)d_in[5];
    const float* in_ln_b = (const float*)d_in[6];
    const float* gat_Wl = (const float*)d_in[7];
    const float* gat_bl = (const float*)d_in[8];
    const float* gat_Wr = (const float*)d_in[9];
    const float* gat_br = (const float*)d_in[10];
    const float* gat_att = (const float*)d_in[11];
    const float* gat_bias = (const float*)d_in[12];
    const float* gat_ln_g = (const float*)d_in[13];
    const float* gat_ln_b = (const float*)d_in[14];
    const float* tr_Wq = (const float*)d_in[15];
    const float* tr_bq = (const float*)d_in[16];
    const float* tr_Wk = (const float*)d_in[17];
    const float* tr_bk = (const float*)d_in[18];
    const float* tr_Wv = (const float*)d_in[19];
    const float* tr_bv = (const float*)d_in[20];
    const float* tr_Wskip = (const float*)d_in[21];
    const float* tr_bskip = (const float*)d_in[22];
    const float* tr_ln_g = (const float*)d_in[23];
    const float* tr_ln_b = (const float*)d_in[24];
    const float* out_W = (const float*)d_in[25];
    const float* out_b = (const float*)d_in[26];
    const float* out_ln_g = (const float*)d_in[27];
    const float* out_ln_b = (const float*)d_in[28];

    int N = in_sizes[0] / F_IN;
    int E = in_sizes[1] / 2;
    int G = out_size / (2 * HID);
    const int* src = ei;
    const int* dst = ei + E;

    float *hP, *bigP, *tP, *geP, *wgP, *bgP, *wtP, *btP;
    cudaGetSymbolAddress((void**)&hP, g_h);
    cudaGetSymbolAddress((void**)&bigP, g_big);
    cudaGetSymbolAddress((void**)&tP, g_t);
    cudaGetSymbolAddress((void**)&geP, g_ge);
    cudaGetSymbolAddress((void**)&wgP, g_wg);
    cudaGetSymbolAddress((void**)&bgP, g_bg);
    cudaGetSymbolAddress((void**)&wtP, g_wt);
    cudaGetSymbolAddress((void**)&btP, g_bt);

    // 0: pack GAT weights
    pack_gat_kernel<<<(NLAYER * HID * 512 + 255) / 256, 256>>>(gat_Wl, gat_bl, gat_Wr, gat_br);
    // 1-2: input embed (K=34, fp32)
    run_gemm_f32(x, in_W, in_b, tP, N, F_IN, HID);
    ln_kernel<HID, true><<<N, HID>>>(tP, in_ln_g, in_ln_b, hP);
    // 3: first GAT GEMM (profiled launch slot)
    run_gemm_tc(hP, wgP, bgP, bigP, N, HID, 512);
    // 4: init pools/deg
    int initN = (G * HID > N) ? G * HID : N;
    init_kernel<<<(initN + 255) / 256, 256>>>(N, G);
    // 5-7: build CSR by destination
    deg_kernel<<<(E + 255) / 256, 256>>>(dst, E);
    scan_kernel<<<1, 1024>>>(N);
    scatter_kernel<<<(E + 255) / 256, 256>>>(src, dst, E);
    // 8: GAT layer 0 aggregate
    gat_kernel<<<N, 64>>>(bigP, gat_att, gat_bias, gat_ln_g, gat_ln_b, hP);
    // layers 1..4
    for (int l = 1; l < NLAYER; l++) {
        run_gemm_tc(hP, wgP + (size_t)l * HID * 512, bgP + (size_t)l * 512, bigP, N, HID, 512);
        gat_kernel<<<N, 64>>>(bigP, gat_att + (size_t)l * HID, gat_bias + (size_t)l * HID,
                              gat_ln_g + (size_t)l * HID, gat_ln_b + (size_t)l * HID, hP);
    }

    // TransformerConv: one packed GEMM -> q|k|v|skip
    pack_tr_kernel<<<(HID * 1024 + 255) / 256, 256>>>(tr_Wq, tr_bq, tr_Wk, tr_bk, tr_Wv, tr_bv,
                                                      tr_Wskip, tr_bskip);
    run_gemm_tc(hP, wtP, btP, bigP, N, HID, 1024);
    trans_kernel<<<N, 64>>>(bigP, tr_ln_g, tr_ln_b, hP);

    // pooling
    pool_kernel<<<N, HID>>>(hP, batch);
    finalize_kernel<<<(G * 2 * HID + 255) / 256, 256>>>(G);

    // output projection (fp32) + LN + GELU
    run_gemm_f32(geP, out_W, out_b, tP, G, 2 * HID, 2 * HID);
    ln_kernel<2 * HID, true><<<G, 2 * HID>>>(tP, out_ln_g, out_ln_b, (float*)d_out);
}